// round 13
// baseline (speedup 1.0000x reference)
#include <cuda_runtime.h>
#include <cuda_bf16.h>
#include <math.h>

// ---------------------------------------------------------------------------
// VectorQuantiser forward, GB300 sm_103a
// z [16,64,64,64] f32 (4194304), embedding [1024,64] f32, embed_prob [1024]
// Tokens N = 65536, codes K = 1024, dim D = 64.
// Output (f32, reference order): z_q_out [4194304], loss [1], perplexity [1],
//   new_embedding [65536], embed_prob_new [1024], encoding_indices [65536]
// ---------------------------------------------------------------------------

#define N_TOK 65536
#define K_CODE 1024
#define D_DIM 64

#define OFF_ZQ   0
#define OFF_LOSS 4194304
#define OFF_PERP 4194305
#define OFF_EMB  4194306
#define OFF_EPN  4259842
#define OFF_ENC  4260866

// ---- scratch (static device memory; allocation-free) ----
__device__ float              g_e2[K_CODE];
__device__ unsigned long long g_cbest[K_CODE * 256];   // [code][block]
__device__ __align__(16) int  g_idx[N_TOK];
__device__ int                g_hist[K_CODE];
__device__ float              g_partial[512];

// ---- helpers ----
__device__ __forceinline__ unsigned long long fma_f32x2(
    unsigned long long a, unsigned long long b, unsigned long long c) {
    unsigned long long d;
    asm("fma.rn.f32x2 %0, %1, %2, %3;" : "=l"(d) : "l"(a), "l"(b), "l"(c));
    return d;
}
__device__ __forceinline__ unsigned long long pk2(float lo, float hi) {
    unsigned long long r;
    asm("mov.b64 %0, {%1, %2};" : "=l"(r) : "f"(lo), "f"(hi));
    return r;
}
__device__ __forceinline__ float upk_sum(unsigned long long v) {
    float lo, hi;
    asm("mov.b64 {%0,%1}, %2;" : "=f"(lo), "=f"(hi) : "l"(v));
    return __fadd_rn(lo, hi);
}

// ---------------------------------------------------------------------------
// Kernel 1: prep — codebook squared norms (frozen chain) + zero histogram
// ---------------------------------------------------------------------------
__global__ void vq_prep(const float* __restrict__ emb) {
    int k = blockIdx.x * 256 + threadIdx.x;   // grid 4 x 256
    float s = 0.f;
    const float* e = emb + k * D_DIM;
#pragma unroll
    for (int j = 0; j < D_DIM; j++) s = fmaf(e[j], e[j], s);
    g_e2[k] = s;
    g_hist[k] = 0;
}

// ---------------------------------------------------------------------------
// Kernel 2: main — HALF-SPLIT layout. 256 blocks x 128 threads, 256 tokens
// per block. A lane PAIR owns 4 tokens: even lane runs the exact a0 subchain
// (even pair-indices), odd lane the exact a1 subchain; combined with one
// shfl + __fadd_rn, reproducing dot=(l0+h0)+(l1+h1) bit-exactly. Each lane
// reads only 128B per code (halved crossbar traffic). SMEM row layout
// interleaves A/B halves at 16B granularity (bank-disjoint halves).
// zn2: frozen full-row sequential chain per token. d-chain frozen.
// ---------------------------------------------------------------------------
__global__ void __launch_bounds__(128, 2) vq_main(
    const float* __restrict__ z, const float* __restrict__ emb,
    float* __restrict__ out) {
    __shared__ __align__(16) float sh_e[128 * D_DIM];   // 32 KB interleaved
    __shared__ float sh_e2[128];
    __shared__ __align__(16) unsigned long long sbest[128];
    __shared__ int sh_hist[K_CODE];

    const int tid = threadIdx.x;
    const int hs = tid & 1;                   // 0 = a0-half, 1 = a1-half
    const int q = tid >> 1;                   // pair id 0..63
    const int nbase = blockIdx.x * 256;
    const int pbase = nbase & 4095;
    const int b = nbase >> 12;
    const float* zb = z + ((size_t)b << 18) + pbase + q;

    const unsigned sb_base = (unsigned)__cvta_generic_to_shared(sbest);
    unsigned long long* sh_e64 = (unsigned long long*)sh_e;

#pragma unroll
    for (int i = 0; i < 8; i++) sh_hist[tid + i * 128] = 0;

    // Preload: 4 tokens per pair (n = nbase + q + 64j). Every lane loads the
    // full row (frozen zn2 chain c=0..63), keeps only its half packed.
    unsigned long long zh[64];                // [j][m] 4 x 16 u64 halves
    float nzn2[4];
#pragma unroll
    for (int j = 0; j < 4; j++) {
        const float* zp = zb + (j << 6);
        float zn2 = 0.f;
#pragma unroll
        for (int m = 0; m < 16; m++) {
            float a0 = zp[(size_t)(4 * m) << 12];
            float a1 = zp[(size_t)(4 * m + 1) << 12];
            float c0 = zp[(size_t)(4 * m + 2) << 12];
            float c1 = zp[(size_t)(4 * m + 3) << 12];
            zn2 = fmaf(a0, a0, zn2);
            zn2 = fmaf(a1, a1, zn2);
            zn2 = fmaf(c0, c0, zn2);
            zn2 = fmaf(c1, c1, zn2);
            unsigned long long pA = pk2(a0, a1);   // pair 2m   (a0-half)
            unsigned long long pB = pk2(c0, c1);   // pair 2m+1 (a1-half)
            zh[j * 16 + m] = hs ? pB : pA;
        }
        nzn2[j] = -zn2;
    }

    unsigned bestu[4] = {0, 0, 0, 0};
    int bestk[4] = {0, 0, 0, 0};

    for (int ch = 0; ch < 8; ch++) {
        const int kbase = ch << 7;
        // copy chunk: global float4 f holds pairs 2f (->A slot f) and
        // 2f+1 (->B slot f). Interleaved: A word w at byte 32w, B at 32w+16.
        const float4* src = (const float4*)(emb + (ch << 13));
#pragma unroll
        for (int r = 0; r < 16; r++) {
            int idx = tid + (r << 7);
            float4 v = src[idx];
            int row = idx >> 4, f = idx & 15;
            int base = row * 32 + ((f >> 1) << 2) + (f & 1);
            sh_e64[base] = pk2(v.x, v.y);         // A slot f
            sh_e64[base + 2] = pk2(v.z, v.w);     // B slot f
        }
        sh_e2[tid] = g_e2[kbase + tid];
        sbest[tid] = 0ULL;
        __syncthreads();

#pragma unroll 1
        for (int kc = 0; kc < 128; kc++) {
            const ulonglong2* ep = (const ulonglong2*)sh_e64 + kc * 16 + hs;
            unsigned long long ac0 = 0ULL, ac1 = 0ULL, ac2 = 0ULL, ac3 = 0ULL;
#pragma unroll
            for (int w = 0; w < 8; w++) {
                ulonglong2 v = ep[2 * w];         // LDS.128, bank-disjoint
                ac0 = fma_f32x2(zh[2 * w], v.x, ac0);
                ac1 = fma_f32x2(zh[16 + 2 * w], v.x, ac1);
                ac2 = fma_f32x2(zh[32 + 2 * w], v.x, ac2);
                ac3 = fma_f32x2(zh[48 + 2 * w], v.x, ac3);
                ac0 = fma_f32x2(zh[2 * w + 1], v.y, ac0);
                ac1 = fma_f32x2(zh[16 + 2 * w + 1], v.y, ac1);
                ac2 = fma_f32x2(zh[32 + 2 * w + 1], v.y, ac2);
                ac3 = fma_f32x2(zh[48 + 2 * w + 1], v.y, ac3);
            }
            float e2 = sh_e2[kc];
            float ds0 = upk_sum(ac0), ds1 = upk_sum(ac1);
            float ds2 = upk_sum(ac2), ds3 = upk_sum(ac3);
            // partner's (l1+h1) from odd lane to even lane
            float db0 = __shfl_down_sync(0xFFFFFFFFu, ds0, 1);
            float db1 = __shfl_down_sync(0xFFFFFFFFu, ds1, 1);
            float db2 = __shfl_down_sync(0xFFFFFFFFu, ds2, 1);
            float db3 = __shfl_down_sync(0xFFFFFFFFu, ds3, 1);
            int k = kbase + kc;
            // frozen combine + d chain (meaningful on even lanes)
            float d0 = __fadd_rn(__fsub_rn(nzn2[0], e2),
                                 __fmul_rn(2.0f, __fadd_rn(ds0, db0)));
            float d1 = __fadd_rn(__fsub_rn(nzn2[1], e2),
                                 __fmul_rn(2.0f, __fadd_rn(ds1, db1)));
            float d2 = __fadd_rn(__fsub_rn(nzn2[2], e2),
                                 __fmul_rn(2.0f, __fadd_rn(ds2, db2)));
            float d3 = __fadd_rn(__fsub_rn(nzn2[3], e2),
                                 __fmul_rn(2.0f, __fadd_rn(ds3, db3)));
            unsigned u0 = ~__float_as_uint(d0);
            unsigned u1 = ~__float_as_uint(d1);
            unsigned u2 = ~__float_as_uint(d2);
            unsigned u3 = ~__float_as_uint(d3);
            if (u0 > bestu[0]) { bestu[0] = u0; bestk[0] = k; }
            if (u1 > bestu[1]) { bestu[1] = u1; bestk[1] = k; }
            if (u2 > bestu[2]) { bestu[2] = u2; bestk[2] = k; }
            if (u3 > bestu[3]) { bestu[3] = u3; bestk[3] = k; }
            // per-code argmax: strict > keeps lowest j (lowest token)
            unsigned uc = u0; int sel = 0;
            if (u1 > uc) { uc = u1; sel = 1; }
            if (u2 > uc) { uc = u2; sel = 2; }
            if (u3 > uc) { uc = u3; sel = 3; }
            if (hs) uc = 0;                     // odd lanes never win
            unsigned wmax = __reduce_max_sync(0xFFFFFFFFu, uc);
            unsigned tokn = ~((unsigned)(nbase + q + (sel << 6)));
            unsigned pass = (uc == wmax);
            unsigned long long pkv = ((unsigned long long)wmax << 32) | tokn;
            asm volatile(
                "{\n\t.reg .pred p;\n\t.reg .u64 t;\n\t"
                "setp.ne.u32 p, %0, 0;\n\t"
                "@p atom.shared.max.u64 t, [%1], %2;\n\t}"
                :: "r"(pass), "r"(sb_base + kc * 8), "l"(pkv));
        }
        __syncthreads();
        g_cbest[(size_t)(kbase + tid) * 256 + blockIdx.x] = sbest[tid];
        __syncthreads();
    }

    if (!hs) {
#pragma unroll
        for (int j = 0; j < 4; j++) {
            int n = nbase + q + (j << 6);
            g_idx[n] = bestk[j];
            out[OFF_ENC + n] = (float)bestk[j];
            atomicAdd(&sh_hist[bestk[j]], 1);
        }
    }
    __syncthreads();
#pragma unroll
    for (int i = 0; i < 8; i++) {
        int v = sh_hist[tid + i * 128];
        if (v) atomicAdd(&g_hist[tid + i * 128], v);
    }
}

// ---------------------------------------------------------------------------
// Kernel 3: per-code best + embed_prob_new + decay + new_embedding (merged).
// BIT-IDENTICAL to R12.
// ---------------------------------------------------------------------------
__global__ void vq_closest_emb(float* __restrict__ out,
                               const float* __restrict__ z,
                               const float* __restrict__ emb,
                               const float* __restrict__ prob) {
    __shared__ unsigned long long red[64];
    __shared__ int s_cn;
    int k = blockIdx.x;                       // grid 1024 x 64
    int t = threadIdx.x;
    unsigned long long m = 0ULL;
    const unsigned long long* row = g_cbest + (size_t)k * 256;
#pragma unroll
    for (int i = 0; i < 4; i++) {
        unsigned long long v = row[i * 64 + t];
        if (v > m) m = v;
    }
    red[t] = m;
    __syncthreads();
    if (t < 32) {
        unsigned long long v = red[t + 32];
        if (v > m) m = v;
#pragma unroll
        for (int s = 16; s > 0; s >>= 1) {
            unsigned long long o = __shfl_xor_sync(0xFFFFFFFFu, m, s);
            if (o > m) m = o;
        }
        if (t == 0) s_cn = (int)(~((unsigned)m));
    }

    float avg = (float)g_hist[k] * (1.0f / 65536.0f);   // exact /2^16
    float epn = __fadd_rn(__fmul_rn(prob[k], 0.99f), __fmul_rn(0.01f, avg));
    if (t == 0) out[OFF_EPN + k] = epn;
    float a = __fmul_rn(epn, 1024.0f);
    a = __fmul_rn(a, 10.0f);
    a = a / 0.01f;
    float decay = expf(__fsub_rn(-a, 1e-3f));
    float omd = __fsub_rn(1.0f, decay);
    __syncthreads();

    int cn = s_cn;
    int cb = cn >> 12, cp = cn & 4095;
    float zc = z[((size_t)cb << 18) + ((size_t)t << 12) + cp];
    float e = emb[k * D_DIM + t];
    out[OFF_EMB + k * D_DIM + t] =
        __fadd_rn(__fmul_rn(e, omd), __fmul_rn(zc, decay));
}

// ---------------------------------------------------------------------------
// Kernel 4: z_q_out + loss partials — block-staged gather (R12 form).
// ---------------------------------------------------------------------------
__global__ void __launch_bounds__(128) vq_zq_loss(
    float* __restrict__ out, const float* __restrict__ z,
    const float* __restrict__ emb) {
    __shared__ float se[128 * 65];            // 33 KB padded rows
    __shared__ float red[128];

    const int tid = threadIdx.x;
    const int lane = tid & 31;
    const int wrp = tid >> 5;
    const int nbase = blockIdx.x * 128;
    const int b = nbase >> 12;
    const int p = (nbase & 4095) + tid;

    const int myidx = g_idx[nbase + tid];

#pragma unroll 4
    for (int j = 0; j < 32; j++) {
        int tok = wrp * 32 + j;
        int id = __shfl_sync(0xFFFFFFFFu, myidx, j);
        float2 ev = *(const float2*)(emb + (id << 6) + lane * 2);
        se[tok * 65 + lane * 2]     = ev.x;
        se[tok * 65 + lane * 2 + 1] = ev.y;
    }
    __syncthreads();

    const size_t ibase = ((size_t)b << 18) + p;
    float ls = 0.f;
#pragma unroll 4
    for (int c = 0; c < 64; c++) {
        size_t i = ibase + ((size_t)c << 12);
        float zv = z[i];
        float ev = se[tid * 65 + c];
        float diff = __fsub_rn(ev, zv);       // frozen chain
        out[OFF_ZQ + i] = __fadd_rn(zv, diff);
        ls = fmaf(diff, diff, ls);
    }
#pragma unroll
    for (int s = 16; s > 0; s >>= 1)
        ls += __shfl_xor_sync(0xFFFFFFFFu, ls, s);
    if (lane == 0) red[wrp] = ls;
    __syncthreads();
    if (tid == 0)
        g_partial[blockIdx.x] = (red[0] + red[1]) + (red[2] + red[3]);
}

// ---------------------------------------------------------------------------
// Kernel 5: final — perplexity + loss, shfl-based (R12 form)
// ---------------------------------------------------------------------------
__global__ void vq_final(float* __restrict__ out) {
    __shared__ float sp[32];
    __shared__ double sl[32];
    int t = threadIdx.x;                      // grid 1 x 1024
    int lane = t & 31, wrp = t >> 5;
    float avg = (float)g_hist[t] * (1.0f / 65536.0f);
    float pv = __fmul_rn(avg, logf(__fadd_rn(avg, 1e-10f)));
    double lv = (t < 512) ? (double)g_partial[t] : 0.0;
#pragma unroll
    for (int s = 16; s > 0; s >>= 1) {
        pv += __shfl_xor_sync(0xFFFFFFFFu, pv, s);
        lv += __shfl_xor_sync(0xFFFFFFFFu, lv, s);
    }
    if (lane == 0) { sp[wrp] = pv; sl[wrp] = lv; }
    __syncthreads();
    if (wrp == 0) {
        float p2 = sp[lane];
        double l2 = sl[lane];
#pragma unroll
        for (int s = 16; s > 0; s >>= 1) {
            p2 += __shfl_xor_sync(0xFFFFFFFFu, p2, s);
            l2 += __shfl_xor_sync(0xFFFFFFFFu, l2, s);
        }
        if (lane == 0) {
            out[OFF_PERP] = expf(-p2);
            out[OFF_LOSS] = (float)(1.25 * l2 / 4194304.0);  // (1+BETA)*mean
        }
    }
}

// ---------------------------------------------------------------------------
extern "C" void kernel_launch(void* const* d_in, const int* in_sizes, int n_in,
                              void* d_out, int out_size) {
    const float* z = nullptr;
    const float* emb = nullptr;
    const float* prob = nullptr;
    for (int i = 0; i < n_in; i++) {
        if (in_sizes[i] == 4194304) z = (const float*)d_in[i];
        else if (in_sizes[i] == 65536) emb = (const float*)d_in[i];
        else if (in_sizes[i] == 1024) prob = (const float*)d_in[i];
    }
    float* out = (float*)d_out;

    vq_prep<<<4, 256>>>(emb);
    vq_main<<<256, 128>>>(z, emb, out);
    vq_closest_emb<<<1024, 64>>>(out, z, emb, prob);
    vq_zq_loss<<<512, 128>>>(out, z, emb);
    vq_final<<<1, 1024>>>(out);
}

// round 14
// speedup vs baseline: 1.1392x; 1.1392x over previous
#include <cuda_runtime.h>
#include <cuda_bf16.h>
#include <math.h>

// ---------------------------------------------------------------------------
// VectorQuantiser forward, GB300 sm_103a
// z [16,64,64,64] f32 (4194304), embedding [1024,64] f32, embed_prob [1024]
// Tokens N = 65536, codes K = 1024, dim D = 64.
// Output (f32, reference order): z_q_out [4194304], loss [1], perplexity [1],
//   new_embedding [65536], embed_prob_new [1024], encoding_indices [65536]
// ---------------------------------------------------------------------------

#define N_TOK 65536
#define K_CODE 1024
#define D_DIM 64

#define OFF_ZQ   0
#define OFF_LOSS 4194304
#define OFF_PERP 4194305
#define OFF_EMB  4194306
#define OFF_EPN  4259842
#define OFF_ENC  4260866

// ---- scratch (static device memory; allocation-free) ----
__device__ float              g_e2[K_CODE];
__device__ unsigned long long g_cbest[K_CODE * 256];   // [code][block]
__device__ __align__(16) int  g_idx[N_TOK];
__device__ int                g_hist[K_CODE];
__device__ float              g_partial[2048];

// ---- helpers ----
__device__ __forceinline__ unsigned long long fma_f32x2(
    unsigned long long a, unsigned long long b, unsigned long long c) {
    unsigned long long d;
    asm("fma.rn.f32x2 %0, %1, %2, %3;" : "=l"(d) : "l"(a), "l"(b), "l"(c));
    return d;
}

// ---------------------------------------------------------------------------
// Kernel 1: prep — codebook squared norms (frozen chain) + zero histogram
// ---------------------------------------------------------------------------
__global__ void vq_prep(const float* __restrict__ emb) {
    int k = blockIdx.x * 256 + threadIdx.x;   // grid 4 x 256
    float s = 0.f;
    const float* e = emb + k * D_DIM;
#pragma unroll
    for (int j = 0; j < D_DIM; j++) s = fmaf(e[j], e[j], s);
    g_e2[k] = s;
    g_hist[k] = 0;
}

// ---------------------------------------------------------------------------
// Kernel 2: main — distances + dual argmax + enc + histogram.
// BIT-IDENTICAL to the R12-passing kernel (288.4 us total). Untouched.
// ---------------------------------------------------------------------------
__global__ void __launch_bounds__(128, 2) vq_main(
    const float* __restrict__ z, const float* __restrict__ emb,
    float* __restrict__ out) {
    __shared__ __align__(16) float sh_e[128 * D_DIM];   // 32 KB
    __shared__ float sh_e2[128];
    __shared__ __align__(16) unsigned long long sbest[128];
    __shared__ int sh_hist[K_CODE];

    const int tid = threadIdx.x;
    const int n0 = blockIdx.x * 128 + tid;              // 0..32767
    const int n1 = n0 + 32768;                          // 32768..65535
    const float* zb0 = z + ((size_t)(n0 >> 12) << 18) + (n0 & 4095);
    const float* zb1 = zb0 + ((size_t)8 << 18);         // +8 batches

    const unsigned sb_base = (unsigned)__cvta_generic_to_shared(sbest);

#pragma unroll
    for (int i = 0; i < 8; i++) sh_hist[tid + i * 128] = 0;

    unsigned long long zpk0[32], zpk1[32];
    float zn2a = 0.f, zn2b = 0.f;
#pragma unroll
    for (int t = 0; t < 32; t++) {
        float a0 = zb0[(size_t)(2 * t) << 12];
        float a1 = zb0[(size_t)(2 * t + 1) << 12];
        zn2a = fmaf(a0, a0, zn2a);
        zn2a = fmaf(a1, a1, zn2a);
        asm("mov.b64 %0, {%1, %2};" : "=l"(zpk0[t]) : "f"(a0), "f"(a1));
        float c0 = zb1[(size_t)(2 * t) << 12];
        float c1 = zb1[(size_t)(2 * t + 1) << 12];
        zn2b = fmaf(c0, c0, zn2b);
        zn2b = fmaf(c1, c1, zn2b);
        asm("mov.b64 %0, {%1, %2};" : "=l"(zpk1[t]) : "f"(c0), "f"(c1));
    }
    const float nzn20 = -zn2a;
    const float nzn21 = -zn2b;
    const unsigned ntok0 = ~((unsigned)n0);
    const unsigned ntok1 = ~((unsigned)n1);

    unsigned best_u0 = 0, best_u1 = 0;
    int bestk0 = 0, bestk1 = 0;

    for (int ch = 0; ch < 8; ch++) {
        const int kbase = ch << 7;
        const float4* src = (const float4*)(emb + (ch << 13));
        float4* dst = (float4*)sh_e;
#pragma unroll
        for (int r = 0; r < 16; r++) dst[tid + (r << 7)] = src[tid + (r << 7)];
        sh_e2[tid] = g_e2[kbase + tid];
        sbest[tid] = 0ULL;
        __syncthreads();

#pragma unroll 2
        for (int kc = 0; kc < 128; kc++) {
            float e2 = sh_e2[kc];
            const ulonglong2* ep = (const ulonglong2*)(sh_e + (kc << 6));
            unsigned long long a0 = 0ULL, a1 = 0ULL;    // token0
            unsigned long long b0 = 0ULL, b1 = 0ULL;    // token1
#pragma unroll
            for (int t = 0; t < 8; t++) {
                ulonglong2 e01 = ep[2 * t];       // LDS.128 broadcast
                ulonglong2 e23 = ep[2 * t + 1];
                a0 = fma_f32x2(zpk0[4 * t + 0], e01.x, a0);
                a1 = fma_f32x2(zpk0[4 * t + 1], e01.y, a1);
                b0 = fma_f32x2(zpk1[4 * t + 0], e01.x, b0);
                b1 = fma_f32x2(zpk1[4 * t + 1], e01.y, b1);
                a0 = fma_f32x2(zpk0[4 * t + 2], e23.x, a0);
                a1 = fma_f32x2(zpk0[4 * t + 3], e23.y, a1);
                b0 = fma_f32x2(zpk1[4 * t + 2], e23.x, b0);
                b1 = fma_f32x2(zpk1[4 * t + 3], e23.y, b1);
            }
            float l0, h0, l1, h1, m0, g0, m1, g1;
            asm("mov.b64 {%0,%1}, %2;" : "=f"(l0), "=f"(h0) : "l"(a0));
            asm("mov.b64 {%0,%1}, %2;" : "=f"(l1), "=f"(h1) : "l"(a1));
            asm("mov.b64 {%0,%1}, %2;" : "=f"(m0), "=f"(g0) : "l"(b0));
            asm("mov.b64 {%0,%1}, %2;" : "=f"(m1), "=f"(g1) : "l"(b1));
            float dot0 = (l0 + h0) + (l1 + h1);         // frozen combine
            float dot1 = (m0 + g0) + (m1 + g1);
            float d0 = __fadd_rn(__fsub_rn(nzn20, e2), __fmul_rn(2.0f, dot0));
            float d1 = __fadd_rn(__fsub_rn(nzn21, e2), __fmul_rn(2.0f, dot1));
            int k = kbase + kc;

            unsigned u0 = ~__float_as_uint(d0);         // d<0: monotone key
            unsigned u1 = ~__float_as_uint(d1);
            if (u0 > best_u0) { best_u0 = u0; bestk0 = k; }
            if (u1 > best_u1) { best_u1 = u1; bestk1 = k; }

            unsigned uc = u0 > u1 ? u0 : u1;
            unsigned wmax = __reduce_max_sync(0xFFFFFFFFu, uc);
            unsigned tokn = (u0 == wmax) ? ntok0 : ntok1;
            unsigned pass = (uc == wmax);
            unsigned long long pk = ((unsigned long long)wmax << 32) | tokn;
            asm volatile(
                "{\n\t.reg .pred p;\n\t.reg .u64 t;\n\t"
                "setp.ne.u32 p, %0, 0;\n\t"
                "@p atom.shared.max.u64 t, [%1], %2;\n\t}"
                :: "r"(pass), "r"(sb_base + kc * 8), "l"(pk));
        }
        __syncthreads();
        g_cbest[(size_t)(kbase + tid) * 256 + blockIdx.x] = sbest[tid];
        __syncthreads();
    }

    g_idx[n0] = bestk0;
    g_idx[n1] = bestk1;
    out[OFF_ENC + n0] = (float)bestk0;
    out[OFF_ENC + n1] = (float)bestk1;
    atomicAdd(&sh_hist[bestk0], 1);
    atomicAdd(&sh_hist[bestk1], 1);
    __syncthreads();
#pragma unroll
    for (int i = 0; i < 8; i++) {
        int v = sh_hist[tid + i * 128];
        if (v) atomicAdd(&g_hist[tid + i * 128], v);
    }
}

// ---------------------------------------------------------------------------
// Kernel 3: per-code best + embed_prob_new + decay + new_embedding (merged).
// BIT-IDENTICAL to R12.
// ---------------------------------------------------------------------------
__global__ void vq_closest_emb(float* __restrict__ out,
                               const float* __restrict__ z,
                               const float* __restrict__ emb,
                               const float* __restrict__ prob) {
    __shared__ unsigned long long red[64];
    __shared__ int s_cn;
    int k = blockIdx.x;                       // grid 1024 x 64
    int t = threadIdx.x;
    unsigned long long m = 0ULL;
    const unsigned long long* row = g_cbest + (size_t)k * 256;
#pragma unroll
    for (int i = 0; i < 4; i++) {
        unsigned long long v = row[i * 64 + t];
        if (v > m) m = v;
    }
    red[t] = m;
    __syncthreads();
    if (t < 32) {
        unsigned long long v = red[t + 32];
        if (v > m) m = v;
#pragma unroll
        for (int s = 16; s > 0; s >>= 1) {
            unsigned long long o = __shfl_xor_sync(0xFFFFFFFFu, m, s);
            if (o > m) m = o;
        }
        if (t == 0) s_cn = (int)(~((unsigned)m));
    }

    float avg = (float)g_hist[k] * (1.0f / 65536.0f);   // exact /2^16
    float epn = __fadd_rn(__fmul_rn(prob[k], 0.99f), __fmul_rn(0.01f, avg));
    if (t == 0) out[OFF_EPN + k] = epn;
    float a = __fmul_rn(epn, 1024.0f);
    a = __fmul_rn(a, 10.0f);
    a = a / 0.01f;
    float decay = expf(__fsub_rn(-a, 1e-3f));
    float omd = __fsub_rn(1.0f, decay);
    __syncthreads();

    int cn = s_cn;
    int cb = cn >> 12, cp = cn & 4095;
    float zc = z[((size_t)cb << 18) + ((size_t)t << 12) + cp];
    float e = emb[k * D_DIM + t];
    out[OFF_EMB + k * D_DIM + t] =
        __fadd_rn(__fmul_rn(e, omd), __fmul_rn(zc, decay));
}

// ---------------------------------------------------------------------------
// Kernel 4: z_q_out + loss partials — HIGH-OCCUPANCY staged gather.
// 2048 blocks x 128 threads; block owns 32 consecutive tokens (smem 8.4 KB,
// ~14 CTAs/SM). Phase 1: each warp stages 8 emb rows (shfl-broadcast id,
// 256B coalesced row loads). Phase 2: thread (cg,tok) does 16 channels of
// token tok — coalesced z/out, stride-65 conflict-free LDS.
// Frozen per-element chain.
// ---------------------------------------------------------------------------
__global__ void __launch_bounds__(128) vq_zq_loss(
    float* __restrict__ out, const float* __restrict__ z,
    const float* __restrict__ emb) {
    __shared__ float se[32 * 65];             // 8.3 KB padded rows
    __shared__ float red[4];

    const int tid = threadIdx.x;
    const int lane = tid & 31;
    const int wrp = tid >> 5;
    const int nbase = blockIdx.x * 32;        // 32 consecutive tokens
    const int b = nbase >> 12;
    const int pbase = nbase & 4095;

    const int idxv = g_idx[nbase + lane];     // each warp: all 32 ids

    // Phase 1: warp w stages rows w*8 .. w*8+7.
#pragma unroll
    for (int j = 0; j < 8; j++) {
        int row = wrp * 8 + j;
        int id = __shfl_sync(0xFFFFFFFFu, idxv, row);
        float2 ev = *(const float2*)(emb + (id << 6) + lane * 2);
        se[row * 65 + lane * 2]     = ev.x;
        se[row * 65 + lane * 2 + 1] = ev.y;
    }
    __syncthreads();

    // Phase 2: cg = wrp handles channels cg*16 .. cg*16+15 of token lane.
    const int tok = lane;
    const size_t ibase = ((size_t)b << 18) + pbase + tok;
    float ls = 0.f;
#pragma unroll
    for (int cc = 0; cc < 16; cc++) {
        int c = wrp * 16 + cc;
        size_t i = ibase + ((size_t)c << 12);
        float zv = z[i];
        float ev = se[tok * 65 + c];
        float diff = __fsub_rn(ev, zv);       // frozen chain
        out[OFF_ZQ + i] = __fadd_rn(zv, diff);
        ls = fmaf(diff, diff, ls);
    }
#pragma unroll
    for (int s = 16; s > 0; s >>= 1)
        ls += __shfl_xor_sync(0xFFFFFFFFu, ls, s);
    if (lane == 0) red[wrp] = ls;
    __syncthreads();
    if (tid == 0)
        g_partial[blockIdx.x] = (red[0] + red[1]) + (red[2] + red[3]);
}

// ---------------------------------------------------------------------------
// Kernel 5: final — perplexity + loss, shfl-based
// ---------------------------------------------------------------------------
__global__ void vq_final(float* __restrict__ out) {
    __shared__ float sp[32];
    __shared__ double sl[32];
    int t = threadIdx.x;                      // grid 1 x 1024
    int lane = t & 31, wrp = t >> 5;
    float avg = (float)g_hist[t] * (1.0f / 65536.0f);
    float pv = __fmul_rn(avg, logf(__fadd_rn(avg, 1e-10f)));
    double lv = (double)g_partial[t] + (double)g_partial[t + 1024];
#pragma unroll
    for (int s = 16; s > 0; s >>= 1) {
        pv += __shfl_xor_sync(0xFFFFFFFFu, pv, s);
        lv += __shfl_xor_sync(0xFFFFFFFFu, lv, s);
    }
    if (lane == 0) { sp[wrp] = pv; sl[wrp] = lv; }
    __syncthreads();
    if (wrp == 0) {
        float p2 = sp[lane];
        double l2 = sl[lane];
#pragma unroll
        for (int s = 16; s > 0; s >>= 1) {
            p2 += __shfl_xor_sync(0xFFFFFFFFu, p2, s);
            l2 += __shfl_xor_sync(0xFFFFFFFFu, l2, s);
        }
        if (lane == 0) {
            out[OFF_PERP] = expf(-p2);
            out[OFF_LOSS] = (float)(1.25 * l2 / 4194304.0);  // (1+BETA)*mean
        }
    }
}

// ---------------------------------------------------------------------------
extern "C" void kernel_launch(void* const* d_in, const int* in_sizes, int n_in,
                              void* d_out, int out_size) {
    const float* z = nullptr;
    const float* emb = nullptr;
    const float* prob = nullptr;
    for (int i = 0; i < n_in; i++) {
        if (in_sizes[i] == 4194304) z = (const float*)d_in[i];
        else if (in_sizes[i] == 65536) emb = (const float*)d_in[i];
        else if (in_sizes[i] == 1024) prob = (const float*)d_in[i];
    }
    float* out = (float*)d_out;

    vq_prep<<<4, 256>>>(emb);
    vq_main<<<256, 128>>>(z, emb, out);
    vq_closest_emb<<<1024, 64>>>(out, z, emb, prob);
    vq_zq_loss<<<2048, 128>>>(out, z, emb);
    vq_final<<<1, 1024>>>(out);
}